// round 12
// baseline (speedup 1.0000x reference)
#include <cuda_runtime.h>
#include <math.h>
#include <stdint.h>

#define B_SZ   2
#define T_SEQ  2048
#define C_EMB  1024
#define NHEAD  16
#define H_DIM  64
#define M_TOT  (B_SZ * T_SEQ)   // 4096

// Scratch (static device arrays)
__device__ float g_qkv[(size_t)M_TOT * 3 * C_EMB];           // [B,T,3C] fp32
__device__ float g_xt[(size_t)M_TOT * C_EMB];                // tf32 patterns
__device__ float g_wqt[(size_t)3 * C_EMB * C_EMB];
__device__ float g_wpt[(size_t)C_EMB * C_EMB];
__device__ float g_q[(size_t)B_SZ * NHEAD * T_SEQ * H_DIM];  // tf32 pattern, pre-scaled
__device__ float g_k[(size_t)B_SZ * NHEAD * T_SEQ * H_DIM];  // tf32 pattern
__device__ float g_v[(size_t)B_SZ * NHEAD * T_SEQ * H_DIM];  // tf32 pattern
__device__ float g_yt[(size_t)M_TOT * C_EMB];                // tf32 pattern
__device__ float g_cos[T_SEQ * H_DIM];
__device__ float g_sin[T_SEQ * H_DIM];

// ---------------------------------------------------------------------------
__device__ __forceinline__ uint32_t f2tf(float x) {
    uint32_t r;
    asm("cvt.rna.tf32.f32 %0, %1;" : "=r"(r) : "f"(x));
    return r;
}
__device__ __forceinline__ void mma_tf32(float* c,
                                         uint32_t a0, uint32_t a1, uint32_t a2, uint32_t a3,
                                         uint32_t b0, uint32_t b1) {
    asm volatile(
        "mma.sync.aligned.m16n8k8.row.col.f32.tf32.tf32.f32 "
        "{%0,%1,%2,%3}, {%4,%5,%6,%7}, {%8,%9}, {%0,%1,%2,%3};"
        : "+f"(c[0]), "+f"(c[1]), "+f"(c[2]), "+f"(c[3])
        : "r"(a0), "r"(a1), "r"(a2), "r"(a3), "r"(b0), "r"(b1));
}
__device__ __forceinline__ void cp16(uint32_t saddr, const void* g) {
    asm volatile("cp.async.cg.shared.global [%0], [%1], 16;" :: "r"(saddr), "l"(g));
}

// ---------------------------------------------------------------------------
// fp32 -> tf32 bit-pattern convert (vectorized)
// ---------------------------------------------------------------------------
__global__ void cvt_kernel(const float4* __restrict__ src,
                           float4* __restrict__ dst, int n4) {
    int i = blockIdx.x * blockDim.x + threadIdx.x;
    if (i >= n4) return;
    float4 v = src[i];
    v.x = __uint_as_float(f2tf(v.x));
    v.y = __uint_as_float(f2tf(v.y));
    v.z = __uint_as_float(f2tf(v.z));
    v.w = __uint_as_float(f2tf(v.w));
    dst[i] = v;
}

// ---------------------------------------------------------------------------
// RoPE table
// ---------------------------------------------------------------------------
__global__ void rope_table_kernel() {
    int i = blockIdx.x * blockDim.x + threadIdx.x;
    if (i >= T_SEQ * H_DIM) return;
    int t = i >> 6;
    int d = i & 63;
    double f = pow(10000.0, -(double)(d & 31) / 32.0);
    double ang = (double)t * f;
    g_cos[i] = (float)cos(ang);
    g_sin[i] = (float)sin(ang);
}

// ---------------------------------------------------------------------------
// Single-pass tf32 SGEMM: C[M,N] = A[M,K] * B[N,K]^T
// 128x128 block tile, BK=16, 128 threads (4 warps), warp tile 64x64,
// 4-stage cp.async pipeline. Accumulation order identical to prior version.
// ---------------------------------------------------------------------------
#define ALD 20
#define TILE_F (128 * ALD)          // 2560
#define STAGE_F (2 * TILE_F)        // 5120
#define GEMM_STAGES 4
#define GEMM_SMEM_BYTES (GEMM_STAGES * STAGE_F * 4)  // 81920

__device__ __forceinline__ void gemm_load_stage(
    float* sm, int s, const float* A, const float* B,
    int K, int bm, int bn, int k0, int t) {
    float* base = sm + s * STAGE_F;
#pragma unroll
    for (int c = 0; c < 4; c++) {
        int cc = t * 4 + c;            // 0..511
        int row = cc >> 2;             // 0..127
        int k4 = (cc & 3) * 4;
        uint32_t so = (uint32_t)__cvta_generic_to_shared(base + row * ALD + k4);
        cp16(so,              A + (size_t)(bm + row) * K + k0 + k4);
        cp16(so + TILE_F * 4, B + (size_t)(bn + row) * K + k0 + k4);
    }
    asm volatile("cp.async.commit_group;");
}

__global__ __launch_bounds__(128)
void sgemm_tf32(const float* __restrict__ A, const float* __restrict__ B,
                float* __restrict__ Cm, int M, int N, int K) {
    extern __shared__ __align__(16) float sm[];

    int t = threadIdx.x;
    int lane = t & 31, w = t >> 5;      // 4 warps
    int gid = lane >> 2, tig = lane & 3;
    int mw = (w & 1) * 64;              // warp m-offset
    int nw = (w >> 1) * 64;             // warp n-offset
    int bm = blockIdx.y * 128, bn = blockIdx.x * 128;

    float c[4][8][4] = {};

    int nkt = K / 16;
    gemm_load_stage(sm, 0, A, B, K, bm, bn, 0, t);
    gemm_load_stage(sm, 1, A, B, K, bm, bn, 16, t);
    gemm_load_stage(sm, 2, A, B, K, bm, bn, 32, t);

    for (int kt = 0; kt < nkt; kt++) {
        asm volatile("cp.async.wait_group 2;");
        __syncthreads();
        if (kt + 3 < nkt)
            gemm_load_stage(sm, (kt + 3) & 3, A, B, K, bm, bn, (kt + 3) * 16, t);
        else
            asm volatile("cp.async.commit_group;");
        float* As = sm + (kt & 3) * STAGE_F;
        float* Bs = As + TILE_F;

#pragma unroll
        for (int ks = 0; ks < 2; ks++) {
            int kb = ks * 8;
            uint32_t ah[4][4];
#pragma unroll
            for (int mt = 0; mt < 4; mt++) {
                int row = mw + mt * 16 + gid;
                ah[mt][0] = __float_as_uint(As[row * ALD + kb + tig]);
                ah[mt][1] = __float_as_uint(As[(row + 8) * ALD + kb + tig]);
                ah[mt][2] = __float_as_uint(As[row * ALD + kb + tig + 4]);
                ah[mt][3] = __float_as_uint(As[(row + 8) * ALD + kb + tig + 4]);
            }
            uint32_t bh[8][2];
#pragma unroll
            for (int nt = 0; nt < 8; nt++) {
                int n = nw + nt * 8 + gid;
                bh[nt][0] = __float_as_uint(Bs[n * ALD + kb + tig]);
                bh[nt][1] = __float_as_uint(Bs[n * ALD + kb + tig + 4]);
            }
#pragma unroll
            for (int mt = 0; mt < 4; mt++)
#pragma unroll
                for (int nt = 0; nt < 8; nt++)
                    mma_tf32(c[mt][nt], ah[mt][0], ah[mt][1], ah[mt][2], ah[mt][3],
                             bh[nt][0], bh[nt][1]);
        }
    }

#pragma unroll
    for (int mt = 0; mt < 4; mt++) {
        int row = bm + mw + mt * 16 + gid;
#pragma unroll
        for (int nt = 0; nt < 8; nt++) {
            int col = bn + nw + nt * 8 + 2 * tig;
            *(float2*)&Cm[(size_t)row * N + col] =
                make_float2(c[mt][nt][0], c[mt][nt][1]);
            *(float2*)&Cm[(size_t)(row + 8) * N + col] =
                make_float2(c[mt][nt][2], c[mt][nt][3]);
        }
    }
}

// ---------------------------------------------------------------------------
// RoPE + split -> tf32-pattern q (pre-scaled by 1/8), k, v in [B,H,T,D]
// ---------------------------------------------------------------------------
__global__ void rope_split_kernel() {
    int i = blockIdx.x * blockDim.x + threadIdx.x;
    int d = i & 63;
    int h = (i >> 6) & 15;
    int t = (i >> 10) & 2047;
    int b = i >> 21;

    const float* base = g_qkv + (size_t)(b * T_SEQ + t) * (3 * C_EMB);
    float cs = g_cos[t * 64 + d];
    float sn = g_sin[t * 64 + d];

    int o  = h * 64 + d;
    int o2 = h * 64 + ((d < 32) ? (d + 32) : (d - 32));
    float sgn = (d < 32) ? -1.f : 1.f;

    float qv = base[o];
    float qp = base[o2];
    float kv = base[C_EMB + o];
    float kp = base[C_EMB + o2];

    size_t oi = ((size_t)(b * NHEAD + h) * T_SEQ + t) * H_DIM + d;
    g_q[oi] = __uint_as_float(f2tf((qv * cs + sgn * qp * sn) * 0.125f));
    g_k[oi] = __uint_as_float(f2tf(kv * cs + sgn * kp * sn));
    g_v[oi] = __uint_as_float(f2tf(base[2 * C_EMB + o]));
}

// ---------------------------------------------------------------------------
// Flash attention (causal), tf32 mma, cp.async double-buffered K/V.
// Block 256 threads (8 warps), 128 Q rows (16/warp), 64-key tiles.
// P never touches smem: S C-fragments permuted into PV A-fragments via shfl.
// UNCHANGED from R10 (bit-identical numerics).
// ---------------------------------------------------------------------------
#define KS_LD 68
#define VS_LD 72
#define KT_F (64 * KS_LD)                 // 4352
#define VT_F (64 * VS_LD)                 // 4608
#define SM_V_OFF (2 * KT_F)
#define ATTN_SMEM_FLOATS (SM_V_OFF + 2 * VT_F)   // 17920 floats = 71680 B

__device__ __forceinline__ void attn_load_tile(
    float* Ksm, float* Vsm, const float* Kb, const float* Vb, int kt, int t) {
    int row = t >> 2, dc = (t & 3) * 16;
    const float* kp = Kb + ((size_t)kt * 64 + row) * H_DIM + dc;
    const float* vp = Vb + ((size_t)kt * 64 + row) * H_DIM + dc;
    uint32_t ks = (uint32_t)__cvta_generic_to_shared(Ksm + row * KS_LD + dc);
    uint32_t vs = (uint32_t)__cvta_generic_to_shared(Vsm + row * VS_LD + dc);
#pragma unroll
    for (int j = 0; j < 4; j++) {
        cp16(ks + j * 16, kp + j * 4);
        cp16(vs + j * 16, vp + j * 4);
    }
    asm volatile("cp.async.commit_group;");
}

__global__ __launch_bounds__(256)
void attn_mma_kernel(const float* __restrict__ Q, const float* __restrict__ Kg,
                     const float* __restrict__ Vg, float* __restrict__ Yt) {
    extern __shared__ __align__(16) float sm[];

    int t = threadIdx.x;
    int lane = t & 31, w = t >> 5;
    int gid = lane >> 2, tig = lane & 3;
    int qt = blockIdx.x;
    int bh = blockIdx.y;
    int wrow = w * 16;

    const float* Qb = Q  + (size_t)bh * T_SEQ * H_DIM;
    const float* Kb = Kg + (size_t)bh * T_SEQ * H_DIM;
    const float* Vb = Vg + (size_t)bh * T_SEQ * H_DIM;

    int r0g = qt * 128 + wrow + gid;
    int r1g = r0g + 8;
    uint32_t qa[8][4];
    {
        const float* qp0 = Qb + (size_t)r0g * H_DIM;
        const float* qp1 = Qb + (size_t)r1g * H_DIM;
#pragma unroll
        for (int ks = 0; ks < 8; ks++) {
            int kk = ks * 8 + tig;
            qa[ks][0] = __float_as_uint(qp0[kk]);
            qa[ks][1] = __float_as_uint(qp1[kk]);
            qa[ks][2] = __float_as_uint(qp0[kk + 4]);
            qa[ks][3] = __float_as_uint(qp1[kk + 4]);
        }
    }

    float o[8][4] = {};
    float m0 = -INFINITY, m1 = -INFINITY;
    float l0 = 0.f, l1 = 0.f;

    int srcA = (lane & ~3) | (tig >> 1);   // cols tig
    int srcB = srcA + 2;                   // cols tig+4
    bool oddc = (tig & 1);

    int ktmax = 2 * qt + 1;
    attn_load_tile(sm, sm + SM_V_OFF, Kb, Vb, 0, t);

    for (int kt = 0; kt <= ktmax; kt++) {
        asm volatile("cp.async.wait_group 0;");
        __syncthreads();
        if (kt + 1 <= ktmax)
            attn_load_tile(sm + ((kt + 1) & 1) * KT_F,
                           sm + SM_V_OFF + ((kt + 1) & 1) * VT_F,
                           Kb, Vb, kt + 1, t);
        float* Ksm = sm + (kt & 1) * KT_F;
        float* Vsm = sm + SM_V_OFF + (kt & 1) * VT_F;

        // S = Q K^T (scale folded into Q)
        float s[8][4] = {};
#pragma unroll
        for (int ks = 0; ks < 8; ks++) {
            int kk = ks * 8 + tig;
#pragma unroll
            for (int nt = 0; nt < 8; nt++) {
                int n = nt * 8 + gid;
                uint32_t b0 = __float_as_uint(Ksm[n * KS_LD + kk]);
                uint32_t b1 = __float_as_uint(Ksm[n * KS_LD + kk + 4]);
                mma_tf32(s[nt], qa[ks][0], qa[ks][1], qa[ks][2], qa[ks][3], b0, b1);
            }
        }

        if (kt * 64 + 63 > qt * 128 + wrow) {
#pragma unroll
            for (int nt = 0; nt < 8; nt++) {
                int col = kt * 64 + nt * 8 + 2 * tig;
                if (col > r0g)     s[nt][0] = -INFINITY;
                if (col + 1 > r0g) s[nt][1] = -INFINITY;
                if (col > r1g)     s[nt][2] = -INFINITY;
                if (col + 1 > r1g) s[nt][3] = -INFINITY;
            }
        }

        float mt0 = -INFINITY, mt1 = -INFINITY;
#pragma unroll
        for (int nt = 0; nt < 8; nt++) {
            mt0 = fmaxf(mt0, fmaxf(s[nt][0], s[nt][1]));
            mt1 = fmaxf(mt1, fmaxf(s[nt][2], s[nt][3]));
        }
        mt0 = fmaxf(mt0, __shfl_xor_sync(0xffffffffu, mt0, 1));
        mt0 = fmaxf(mt0, __shfl_xor_sync(0xffffffffu, mt0, 2));
        mt1 = fmaxf(mt1, __shfl_xor_sync(0xffffffffu, mt1, 1));
        mt1 = fmaxf(mt1, __shfl_xor_sync(0xffffffffu, mt1, 2));

        float mn0 = fmaxf(m0, mt0), mn1 = fmaxf(m1, mt1);
        float al0 = __expf(m0 - mn0), al1 = __expf(m1 - mn1);
        m0 = mn0; m1 = mn1;

        float ls0 = 0.f, ls1 = 0.f;
#pragma unroll
        for (int nt = 0; nt < 8; nt++) {
            s[nt][0] = __expf(s[nt][0] - mn0);
            s[nt][1] = __expf(s[nt][1] - mn0);
            s[nt][2] = __expf(s[nt][2] - mn1);
            s[nt][3] = __expf(s[nt][3] - mn1);
            ls0 += s[nt][0] + s[nt][1];
            ls1 += s[nt][2] + s[nt][3];
        }
        ls0 += __shfl_xor_sync(0xffffffffu, ls0, 1);
        ls0 += __shfl_xor_sync(0xffffffffu, ls0, 2);
        ls1 += __shfl_xor_sync(0xffffffffu, ls1, 1);
        ls1 += __shfl_xor_sync(0xffffffffu, ls1, 2);
        l0 = l0 * al0 + ls0;
        l1 = l1 * al1 + ls1;

#pragma unroll
        for (int nt = 0; nt < 8; nt++) {
            o[nt][0] *= al0; o[nt][1] *= al0;
            o[nt][2] *= al1; o[nt][3] *= al1;
        }

        // O += P * V ; P fragments built by intra-quad shfl permutation.
#pragma unroll
        for (int ks = 0; ks < 8; ks++) {
            float c0 = __uint_as_float(f2tf(s[ks][0]));
            float c1 = __uint_as_float(f2tf(s[ks][1]));
            float c2 = __uint_as_float(f2tf(s[ks][2]));
            float c3 = __uint_as_float(f2tf(s[ks][3]));
            float a00 = __shfl_sync(0xffffffffu, c0, srcA);
            float a01 = __shfl_sync(0xffffffffu, c1, srcA);
            float a10 = __shfl_sync(0xffffffffu, c2, srcA);
            float a11 = __shfl_sync(0xffffffffu, c3, srcA);
            float b00 = __shfl_sync(0xffffffffu, c0, srcB);
            float b01 = __shfl_sync(0xffffffffu, c1, srcB);
            float b10 = __shfl_sync(0xffffffffu, c2, srcB);
            float b11 = __shfl_sync(0xffffffffu, c3, srcB);
            uint32_t pa0 = __float_as_uint(oddc ? a01 : a00);
            uint32_t pa1 = __float_as_uint(oddc ? a11 : a10);
            uint32_t pa2 = __float_as_uint(oddc ? b01 : b00);
            uint32_t pa3 = __float_as_uint(oddc ? b11 : b10);
            int kk = ks * 8;
#pragma unroll
            for (int nt = 0; nt < 8; nt++) {
                int d = nt * 8 + gid;
                uint32_t b0 = __float_as_uint(Vsm[(kk + tig) * VS_LD + d]);
                uint32_t b1 = __float_as_uint(Vsm[(kk + tig + 4) * VS_LD + d]);
                mma_tf32(o[nt], pa0, pa1, pa2, pa3, b0, b1);
            }
        }
    }

    // finalize: divide by l, write tf32 pattern into Yt [B,T,C]
    float inv0 = 1.f / l0, inv1 = 1.f / l1;
    int b = bh >> 4, h = bh & 15;
    size_t off0 = ((size_t)b * T_SEQ + r0g) * C_EMB + h * 64;
    size_t off1 = ((size_t)b * T_SEQ + r1g) * C_EMB + h * 64;
#pragma unroll
    for (int nt = 0; nt < 8; nt++) {
        int col = nt * 8 + 2 * tig;
        *(float2*)&Yt[off0 + col] =
            make_float2(__uint_as_float(f2tf(o[nt][0] * inv0)),
                        __uint_as_float(f2tf(o[nt][1] * inv0)));
        *(float2*)&Yt[off1 + col] =
            make_float2(__uint_as_float(f2tf(o[nt][2] * inv1)),
                        __uint_as_float(f2tf(o[nt][3] * inv1)));
    }
}

// ---------------------------------------------------------------------------
extern "C" void kernel_launch(void* const* d_in, const int* in_sizes, int n_in,
                              void* d_out, int out_size) {
    const float* x      = (const float*)d_in[0];
    const float* w_qkv  = (const float*)d_in[1];
    const float* w_proj = (const float*)d_in[2];
    float* out = (float*)d_out;

    float *p_qkv, *p_xt, *p_wqt, *p_wpt, *p_q, *p_k, *p_v, *p_yt;
    cudaGetSymbolAddress((void**)&p_qkv, g_qkv);
    cudaGetSymbolAddress((void**)&p_xt, g_xt);
    cudaGetSymbolAddress((void**)&p_wqt, g_wqt);
    cudaGetSymbolAddress((void**)&p_wpt, g_wpt);
    cudaGetSymbolAddress((void**)&p_q, g_q);
    cudaGetSymbolAddress((void**)&p_k, g_k);
    cudaGetSymbolAddress((void**)&p_v, g_v);
    cudaGetSymbolAddress((void**)&p_yt, g_yt);

    // RoPE tables + tf32 pre-conversion
    rope_table_kernel<<<(T_SEQ * H_DIM + 255) / 256, 256>>>();
    cvt_kernel<<<(M_TOT * C_EMB / 4 + 255) / 256, 256>>>(
        (const float4*)x, (float4*)p_xt, M_TOT * C_EMB / 4);
    cvt_kernel<<<(3 * C_EMB * C_EMB / 4 + 255) / 256, 256>>>(
        (const float4*)w_qkv, (float4*)p_wqt, 3 * C_EMB * C_EMB / 4);
    cvt_kernel<<<(C_EMB * C_EMB / 4 + 255) / 256, 256>>>(
        (const float4*)w_proj, (float4*)p_wpt, C_EMB * C_EMB / 4);

    cudaFuncSetAttribute(sgemm_tf32,
                         cudaFuncAttributeMaxDynamicSharedMemorySize, GEMM_SMEM_BYTES);

    // QKV GEMM: [4096,1024] x [3072,1024]^T -> [4096,3072]
    sgemm_tf32<<<dim3((3 * C_EMB) / 128, M_TOT / 128), 128, GEMM_SMEM_BYTES>>>(
        p_xt, p_wqt, p_qkv, M_TOT, 3 * C_EMB, C_EMB);

    // RoPE + split into tf32 [B,H,T,D]
    rope_split_kernel<<<(B_SZ * T_SEQ * C_EMB) / 256, 256>>>();

    // Flash attention
    int smem_bytes = ATTN_SMEM_FLOATS * 4;   // 71680
    cudaFuncSetAttribute(attn_mma_kernel,
                         cudaFuncAttributeMaxDynamicSharedMemorySize, smem_bytes);
    attn_mma_kernel<<<dim3(T_SEQ / 128, B_SZ * NHEAD), 256, smem_bytes>>>(
        p_q, p_k, p_v, p_yt);

    // Proj GEMM: [4096,1024] x [1024,1024]^T -> out
    sgemm_tf32<<<dim3(C_EMB / 128, M_TOT / 128), 128, GEMM_SMEM_BYTES>>>(
        p_yt, p_wpt, out, M_TOT, C_EMB, C_EMB);
}

// round 13
// speedup vs baseline: 1.1083x; 1.1083x over previous
#include <cuda_runtime.h>
#include <math.h>
#include <stdint.h>

#define B_SZ   2
#define T_SEQ  2048
#define C_EMB  1024
#define NHEAD  16
#define H_DIM  64
#define M_TOT  (B_SZ * T_SEQ)   // 4096

// Scratch (static device arrays)
__device__ float g_qkv[(size_t)M_TOT * 3 * C_EMB];           // [B,T,3C] fp32
__device__ float g_xt[(size_t)M_TOT * C_EMB];                // tf32 patterns
__device__ float g_wqt[(size_t)3 * C_EMB * C_EMB];
__device__ float g_wpt[(size_t)C_EMB * C_EMB];
__device__ float g_q[(size_t)B_SZ * NHEAD * T_SEQ * H_DIM];  // tf32 pattern, pre-scaled
__device__ float g_k[(size_t)B_SZ * NHEAD * T_SEQ * H_DIM];  // tf32 pattern
__device__ float g_v[(size_t)B_SZ * NHEAD * T_SEQ * H_DIM];  // tf32 pattern
__device__ float g_yt[(size_t)M_TOT * C_EMB];                // tf32 pattern
__device__ float g_cos[T_SEQ * H_DIM];
__device__ float g_sin[T_SEQ * H_DIM];

// ---------------------------------------------------------------------------
__device__ __forceinline__ uint32_t f2tf(float x) {
    uint32_t r;
    asm("cvt.rna.tf32.f32 %0, %1;" : "=r"(r) : "f"(x));
    return r;
}
__device__ __forceinline__ void mma_tf32(float* c,
                                         uint32_t a0, uint32_t a1, uint32_t a2, uint32_t a3,
                                         uint32_t b0, uint32_t b1) {
    asm volatile(
        "mma.sync.aligned.m16n8k8.row.col.f32.tf32.tf32.f32 "
        "{%0,%1,%2,%3}, {%4,%5,%6,%7}, {%8,%9}, {%0,%1,%2,%3};"
        : "+f"(c[0]), "+f"(c[1]), "+f"(c[2]), "+f"(c[3])
        : "r"(a0), "r"(a1), "r"(a2), "r"(a3), "r"(b0), "r"(b1));
}
__device__ __forceinline__ void cp16(uint32_t saddr, const void* g) {
    asm volatile("cp.async.cg.shared.global [%0], [%1], 16;" :: "r"(saddr), "l"(g));
}

// ---------------------------------------------------------------------------
// fp32 -> tf32 bit-pattern convert (vectorized)
// ---------------------------------------------------------------------------
__global__ void cvt_kernel(const float4* __restrict__ src,
                           float4* __restrict__ dst, int n4) {
    int i = blockIdx.x * blockDim.x + threadIdx.x;
    if (i >= n4) return;
    float4 v = src[i];
    v.x = __uint_as_float(f2tf(v.x));
    v.y = __uint_as_float(f2tf(v.y));
    v.z = __uint_as_float(f2tf(v.z));
    v.w = __uint_as_float(f2tf(v.w));
    dst[i] = v;
}

// ---------------------------------------------------------------------------
// RoPE table
// ---------------------------------------------------------------------------
__global__ void rope_table_kernel() {
    int i = blockIdx.x * blockDim.x + threadIdx.x;
    if (i >= T_SEQ * H_DIM) return;
    int t = i >> 6;
    int d = i & 63;
    double f = pow(10000.0, -(double)(d & 31) / 32.0);
    double ang = (double)t * f;
    g_cos[i] = (float)cos(ang);
    g_sin[i] = (float)sin(ang);
}

// ---------------------------------------------------------------------------
// Single-pass tf32 SGEMM: C[M,N] = A[M,K] * B[N,K]^T
// 128x128 tile, BK=16, 256 threads, warp tile 32x64, 3-stage cp.async.
// (R10 configuration — best measured.)
// ---------------------------------------------------------------------------
#define ALD 20
#define TILE_F (128 * ALD)          // 2560
#define STAGE_F (2 * TILE_F)        // 5120
#define GEMM_SMEM_BYTES (3 * STAGE_F * 4)  // 61440

__device__ __forceinline__ void gemm_load_stage(
    float* sm, int s, const float* A, const float* B,
    int K, int bm, int bn, int k0, int t) {
    float* base = sm + s * STAGE_F;
#pragma unroll
    for (int c = 0; c < 2; c++) {
        int cc = t * 2 + c;
        int row = cc >> 2;
        int k4 = (cc & 3) * 4;
        uint32_t so = (uint32_t)__cvta_generic_to_shared(base + row * ALD + k4);
        cp16(so,              A + (size_t)(bm + row) * K + k0 + k4);
        cp16(so + TILE_F * 4, B + (size_t)(bn + row) * K + k0 + k4);
    }
    asm volatile("cp.async.commit_group;");
}

__global__ __launch_bounds__(256)
void sgemm_tf32(const float* __restrict__ A, const float* __restrict__ B,
                float* __restrict__ Cm, int M, int N, int K) {
    extern __shared__ __align__(16) float sm[];

    int t = threadIdx.x;
    int lane = t & 31, w = t >> 5;
    int gid = lane >> 2, tig = lane & 3;
    int mw = (w & 3) * 32;
    int nw = (w >> 2) * 64;
    int bm = blockIdx.y * 128, bn = blockIdx.x * 128;

    float c[2][8][4] = {};

    int nkt = K / 16;
    gemm_load_stage(sm, 0, A, B, K, bm, bn, 0, t);
    gemm_load_stage(sm, 1, A, B, K, bm, bn, 16, t);

    for (int kt = 0; kt < nkt; kt++) {
        asm volatile("cp.async.wait_group 1;");
        __syncthreads();
        if (kt + 2 < nkt)
            gemm_load_stage(sm, (kt + 2) % 3, A, B, K, bm, bn, (kt + 2) * 16, t);
        else
            asm volatile("cp.async.commit_group;");
        float* As = sm + (kt % 3) * STAGE_F;
        float* Bs = As + TILE_F;

#pragma unroll
        for (int ks = 0; ks < 2; ks++) {
            int kb = ks * 8;
            uint32_t ah[2][4];
#pragma unroll
            for (int mt = 0; mt < 2; mt++) {
                int row = mw + mt * 16 + gid;
                ah[mt][0] = __float_as_uint(As[row * ALD + kb + tig]);
                ah[mt][1] = __float_as_uint(As[(row + 8) * ALD + kb + tig]);
                ah[mt][2] = __float_as_uint(As[row * ALD + kb + tig + 4]);
                ah[mt][3] = __float_as_uint(As[(row + 8) * ALD + kb + tig + 4]);
            }
            uint32_t bh[8][2];
#pragma unroll
            for (int nt = 0; nt < 8; nt++) {
                int n = nw + nt * 8 + gid;
                bh[nt][0] = __float_as_uint(Bs[n * ALD + kb + tig]);
                bh[nt][1] = __float_as_uint(Bs[n * ALD + kb + tig + 4]);
            }
#pragma unroll
            for (int mt = 0; mt < 2; mt++)
#pragma unroll
                for (int nt = 0; nt < 8; nt++)
                    mma_tf32(c[mt][nt], ah[mt][0], ah[mt][1], ah[mt][2], ah[mt][3],
                             bh[nt][0], bh[nt][1]);
        }
    }

#pragma unroll
    for (int mt = 0; mt < 2; mt++) {
        int row = bm + mw + mt * 16 + gid;
#pragma unroll
        for (int nt = 0; nt < 8; nt++) {
            int col = bn + nw + nt * 8 + 2 * tig;
            *(float2*)&Cm[(size_t)row * N + col] =
                make_float2(c[mt][nt][0], c[mt][nt][1]);
            *(float2*)&Cm[(size_t)(row + 8) * N + col] =
                make_float2(c[mt][nt][2], c[mt][nt][3]);
        }
    }
}

// ---------------------------------------------------------------------------
// RoPE + split -> tf32-pattern q (pre-scaled by 1/8), k, v in [B,H,T,D]
// ---------------------------------------------------------------------------
__global__ void rope_split_kernel() {
    int i = blockIdx.x * blockDim.x + threadIdx.x;
    int d = i & 63;
    int h = (i >> 6) & 15;
    int t = (i >> 10) & 2047;
    int b = i >> 21;

    const float* base = g_qkv + (size_t)(b * T_SEQ + t) * (3 * C_EMB);
    float cs = g_cos[t * 64 + d];
    float sn = g_sin[t * 64 + d];

    int o  = h * 64 + d;
    int o2 = h * 64 + ((d < 32) ? (d + 32) : (d - 32));
    float sgn = (d < 32) ? -1.f : 1.f;

    float qv = base[o];
    float qp = base[o2];
    float kv = base[C_EMB + o];
    float kp = base[C_EMB + o2];

    size_t oi = ((size_t)(b * NHEAD + h) * T_SEQ + t) * H_DIM + d;
    g_q[oi] = __uint_as_float(f2tf((qv * cs + sgn * qp * sn) * 0.125f));
    g_k[oi] = __uint_as_float(f2tf(kv * cs + sgn * kp * sn));
    g_v[oi] = __uint_as_float(f2tf(base[2 * C_EMB + o]));
}

// ---------------------------------------------------------------------------
// Flash attention (causal), tf32 mma, cp.async double-buffered K/V.
// Block 256 threads (8 warps), 128 Q rows (16/warp), 64-key tiles.
// Heavy-first scheduling: qt = gridDim.x-1-blockIdx.x so the longest
// CTAs (qt large, 2qt+2 tiles) launch first; tail CTAs are light.
// P never touches smem (shfl permutation). Numerics identical to R10.
// ---------------------------------------------------------------------------
#define KS_LD 68
#define VS_LD 72
#define KT_F (64 * KS_LD)                 // 4352
#define VT_F (64 * VS_LD)                 // 4608
#define SM_V_OFF (2 * KT_F)
#define ATTN_SMEM_FLOATS (SM_V_OFF + 2 * VT_F)   // 17920 floats = 71680 B

__device__ __forceinline__ void attn_load_tile(
    float* Ksm, float* Vsm, const float* Kb, const float* Vb, int kt, int t) {
    int row = t >> 2, dc = (t & 3) * 16;
    const float* kp = Kb + ((size_t)kt * 64 + row) * H_DIM + dc;
    const float* vp = Vb + ((size_t)kt * 64 + row) * H_DIM + dc;
    uint32_t ks = (uint32_t)__cvta_generic_to_shared(Ksm + row * KS_LD + dc);
    uint32_t vs = (uint32_t)__cvta_generic_to_shared(Vsm + row * VS_LD + dc);
#pragma unroll
    for (int j = 0; j < 4; j++) {
        cp16(ks + j * 16, kp + j * 4);
        cp16(vs + j * 16, vp + j * 4);
    }
    asm volatile("cp.async.commit_group;");
}

__global__ __launch_bounds__(256)
void attn_mma_kernel(const float* __restrict__ Q, const float* __restrict__ Kg,
                     const float* __restrict__ Vg, float* __restrict__ Yt) {
    extern __shared__ __align__(16) float sm[];

    int t = threadIdx.x;
    int lane = t & 31, w = t >> 5;
    int gid = lane >> 2, tig = lane & 3;
    int qt = gridDim.x - 1 - blockIdx.x;   // heavy-first
    int bh = blockIdx.y;
    int wrow = w * 16;

    const float* Qb = Q  + (size_t)bh * T_SEQ * H_DIM;
    const float* Kb = Kg + (size_t)bh * T_SEQ * H_DIM;
    const float* Vb = Vg + (size_t)bh * T_SEQ * H_DIM;

    int r0g = qt * 128 + wrow + gid;
    int r1g = r0g + 8;
    uint32_t qa[8][4];
    {
        const float* qp0 = Qb + (size_t)r0g * H_DIM;
        const float* qp1 = Qb + (size_t)r1g * H_DIM;
#pragma unroll
        for (int ks = 0; ks < 8; ks++) {
            int kk = ks * 8 + tig;
            qa[ks][0] = __float_as_uint(qp0[kk]);
            qa[ks][1] = __float_as_uint(qp1[kk]);
            qa[ks][2] = __float_as_uint(qp0[kk + 4]);
            qa[ks][3] = __float_as_uint(qp1[kk + 4]);
        }
    }

    float o[8][4] = {};
    float m0 = -INFINITY, m1 = -INFINITY;
    float l0 = 0.f, l1 = 0.f;

    int srcA = (lane & ~3) | (tig >> 1);   // cols tig
    int srcB = srcA + 2;                   // cols tig+4
    bool oddc = (tig & 1);

    int ktmax = 2 * qt + 1;
    attn_load_tile(sm, sm + SM_V_OFF, Kb, Vb, 0, t);

    for (int kt = 0; kt <= ktmax; kt++) {
        asm volatile("cp.async.wait_group 0;");
        __syncthreads();
        if (kt + 1 <= ktmax)
            attn_load_tile(sm + ((kt + 1) & 1) * KT_F,
                           sm + SM_V_OFF + ((kt + 1) & 1) * VT_F,
                           Kb, Vb, kt + 1, t);
        float* Ksm = sm + (kt & 1) * KT_F;
        float* Vsm = sm + SM_V_OFF + (kt & 1) * VT_F;

        // S = Q K^T (scale folded into Q)
        float s[8][4] = {};
#pragma unroll
        for (int ks = 0; ks < 8; ks++) {
            int kk = ks * 8 + tig;
#pragma unroll
            for (int nt = 0; nt < 8; nt++) {
                int n = nt * 8 + gid;
                uint32_t b0 = __float_as_uint(Ksm[n * KS_LD + kk]);
                uint32_t b1 = __float_as_uint(Ksm[n * KS_LD + kk + 4]);
                mma_tf32(s[nt], qa[ks][0], qa[ks][1], qa[ks][2], qa[ks][3], b0, b1);
            }
        }

        if (kt * 64 + 63 > qt * 128 + wrow) {
#pragma unroll
            for (int nt = 0; nt < 8; nt++) {
                int col = kt * 64 + nt * 8 + 2 * tig;
                if (col > r0g)     s[nt][0] = -INFINITY;
                if (col + 1 > r0g) s[nt][1] = -INFINITY;
                if (col > r1g)     s[nt][2] = -INFINITY;
                if (col + 1 > r1g) s[nt][3] = -INFINITY;
            }
        }

        float mt0 = -INFINITY, mt1 = -INFINITY;
#pragma unroll
        for (int nt = 0; nt < 8; nt++) {
            mt0 = fmaxf(mt0, fmaxf(s[nt][0], s[nt][1]));
            mt1 = fmaxf(mt1, fmaxf(s[nt][2], s[nt][3]));
        }
        mt0 = fmaxf(mt0, __shfl_xor_sync(0xffffffffu, mt0, 1));
        mt0 = fmaxf(mt0, __shfl_xor_sync(0xffffffffu, mt0, 2));
        mt1 = fmaxf(mt1, __shfl_xor_sync(0xffffffffu, mt1, 1));
        mt1 = fmaxf(mt1, __shfl_xor_sync(0xffffffffu, mt1, 2));

        float mn0 = fmaxf(m0, mt0), mn1 = fmaxf(m1, mt1);
        float al0 = __expf(m0 - mn0), al1 = __expf(m1 - mn1);
        m0 = mn0; m1 = mn1;

        float ls0 = 0.f, ls1 = 0.f;
#pragma unroll
        for (int nt = 0; nt < 8; nt++) {
            s[nt][0] = __expf(s[nt][0] - mn0);
            s[nt][1] = __expf(s[nt][1] - mn0);
            s[nt][2] = __expf(s[nt][2] - mn1);
            s[nt][3] = __expf(s[nt][3] - mn1);
            ls0 += s[nt][0] + s[nt][1];
            ls1 += s[nt][2] + s[nt][3];
        }
        ls0 += __shfl_xor_sync(0xffffffffu, ls0, 1);
        ls0 += __shfl_xor_sync(0xffffffffu, ls0, 2);
        ls1 += __shfl_xor_sync(0xffffffffu, ls1, 1);
        ls1 += __shfl_xor_sync(0xffffffffu, ls1, 2);
        l0 = l0 * al0 + ls0;
        l1 = l1 * al1 + ls1;

#pragma unroll
        for (int nt = 0; nt < 8; nt++) {
            o[nt][0] *= al0; o[nt][1] *= al0;
            o[nt][2] *= al1; o[nt][3] *= al1;
        }

        // O += P * V ; P fragments built by intra-quad shfl permutation.
#pragma unroll
        for (int ks = 0; ks < 8; ks++) {
            float c0 = __uint_as_float(f2tf(s[ks][0]));
            float c1 = __uint_as_float(f2tf(s[ks][1]));
            float c2 = __uint_as_float(f2tf(s[ks][2]));
            float c3 = __uint_as_float(f2tf(s[ks][3]));
            float a00 = __shfl_sync(0xffffffffu, c0, srcA);
            float a01 = __shfl_sync(0xffffffffu, c1, srcA);
            float a10 = __shfl_sync(0xffffffffu, c2, srcA);
            float a11 = __shfl_sync(0xffffffffu, c3, srcA);
            float b00 = __shfl_sync(0xffffffffu, c0, srcB);
            float b01 = __shfl_sync(0xffffffffu, c1, srcB);
            float b10 = __shfl_sync(0xffffffffu, c2, srcB);
            float b11 = __shfl_sync(0xffffffffu, c3, srcB);
            uint32_t pa0 = __float_as_uint(oddc ? a01 : a00);
            uint32_t pa1 = __float_as_uint(oddc ? a11 : a10);
            uint32_t pa2 = __float_as_uint(oddc ? b01 : b00);
            uint32_t pa3 = __float_as_uint(oddc ? b11 : b10);
            int kk = ks * 8;
#pragma unroll
            for (int nt = 0; nt < 8; nt++) {
                int d = nt * 8 + gid;
                uint32_t b0 = __float_as_uint(Vsm[(kk + tig) * VS_LD + d]);
                uint32_t b1 = __float_as_uint(Vsm[(kk + tig + 4) * VS_LD + d]);
                mma_tf32(o[nt], pa0, pa1, pa2, pa3, b0, b1);
            }
        }
    }

    // finalize: divide by l, write tf32 pattern into Yt [B,T,C]
    float inv0 = 1.f / l0, inv1 = 1.f / l1;
    int b = bh >> 4, h = bh & 15;
    size_t off0 = ((size_t)b * T_SEQ + r0g) * C_EMB + h * 64;
    size_t off1 = ((size_t)b * T_SEQ + r1g) * C_EMB + h * 64;
#pragma unroll
    for (int nt = 0; nt < 8; nt++) {
        int col = nt * 8 + 2 * tig;
        *(float2*)&Yt[off0 + col] =
            make_float2(__uint_as_float(f2tf(o[nt][0] * inv0)),
                        __uint_as_float(f2tf(o[nt][1] * inv0)));
        *(float2*)&Yt[off1 + col] =
            make_float2(__uint_as_float(f2tf(o[nt][2] * inv1)),
                        __uint_as_float(f2tf(o[nt][3] * inv1)));
    }
}

// ---------------------------------------------------------------------------
extern "C" void kernel_launch(void* const* d_in, const int* in_sizes, int n_in,
                              void* d_out, int out_size) {
    const float* x      = (const float*)d_in[0];
    const float* w_qkv  = (const float*)d_in[1];
    const float* w_proj = (const float*)d_in[2];
    float* out = (float*)d_out;

    float *p_qkv, *p_xt, *p_wqt, *p_wpt, *p_q, *p_k, *p_v, *p_yt;
    cudaGetSymbolAddress((void**)&p_qkv, g_qkv);
    cudaGetSymbolAddress((void**)&p_xt, g_xt);
    cudaGetSymbolAddress((void**)&p_wqt, g_wqt);
    cudaGetSymbolAddress((void**)&p_wpt, g_wpt);
    cudaGetSymbolAddress((void**)&p_q, g_q);
    cudaGetSymbolAddress((void**)&p_k, g_k);
    cudaGetSymbolAddress((void**)&p_v, g_v);
    cudaGetSymbolAddress((void**)&p_yt, g_yt);

    // RoPE tables + tf32 pre-conversion
    rope_table_kernel<<<(T_SEQ * H_DIM + 255) / 256, 256>>>();
    cvt_kernel<<<(M_TOT * C_EMB / 4 + 255) / 256, 256>>>(
        (const float4*)x, (float4*)p_xt, M_TOT * C_EMB / 4);
    cvt_kernel<<<(3 * C_EMB * C_EMB / 4 + 255) / 256, 256>>>(
        (const float4*)w_qkv, (float4*)p_wqt, 3 * C_EMB * C_EMB / 4);
    cvt_kernel<<<(C_EMB * C_EMB / 4 + 255) / 256, 256>>>(
        (const float4*)w_proj, (float4*)p_wpt, C_EMB * C_EMB / 4);

    cudaFuncSetAttribute(sgemm_tf32,
                         cudaFuncAttributeMaxDynamicSharedMemorySize, GEMM_SMEM_BYTES);

    // QKV GEMM: [4096,1024] x [3072,1024]^T -> [4096,3072]
    sgemm_tf32<<<dim3((3 * C_EMB) / 128, M_TOT / 128), 256, GEMM_SMEM_BYTES>>>(
        p_xt, p_wqt, p_qkv, M_TOT, 3 * C_EMB, C_EMB);

    // RoPE + split into tf32 [B,H,T,D]
    rope_split_kernel<<<(B_SZ * T_SEQ * C_EMB) / 256, 256>>>();

    // Flash attention
    int smem_bytes = ATTN_SMEM_FLOATS * 4;   // 71680
    cudaFuncSetAttribute(attn_mma_kernel,
                         cudaFuncAttributeMaxDynamicSharedMemorySize, smem_bytes);
    attn_mma_kernel<<<dim3(T_SEQ / 128, B_SZ * NHEAD), 256, smem_bytes>>>(
        p_q, p_k, p_v, p_yt);

    // Proj GEMM: [4096,1024] x [1024,1024]^T -> out
    sgemm_tf32<<<dim3(C_EMB / 128, M_TOT / 128), 256, GEMM_SMEM_BYTES>>>(
        p_yt, p_wpt, out, M_TOT, C_EMB, C_EMB);
}

// round 14
// speedup vs baseline: 1.1230x; 1.0133x over previous
#include <cuda_runtime.h>
#include <math.h>
#include <stdint.h>

#define B_SZ   2
#define T_SEQ  2048
#define C_EMB  1024
#define NHEAD  16
#define H_DIM  64
#define M_TOT  (B_SZ * T_SEQ)   // 4096

// Scratch (static device arrays)
__device__ float g_xt[(size_t)M_TOT * C_EMB];                // tf32 patterns
__device__ float g_wqt[(size_t)3 * C_EMB * C_EMB];
__device__ float g_wpt[(size_t)C_EMB * C_EMB];
__device__ float g_q[(size_t)B_SZ * NHEAD * T_SEQ * H_DIM];  // tf32 pattern, pre-scaled
__device__ float g_k[(size_t)B_SZ * NHEAD * T_SEQ * H_DIM];  // tf32 pattern
__device__ float g_v[(size_t)B_SZ * NHEAD * T_SEQ * H_DIM];  // tf32 pattern
__device__ float g_yt[(size_t)M_TOT * C_EMB];                // tf32 pattern
__device__ float g_cos[T_SEQ * H_DIM];
__device__ float g_sin[T_SEQ * H_DIM];

// ---------------------------------------------------------------------------
__device__ __forceinline__ uint32_t f2tf(float x) {
    uint32_t r;
    asm("cvt.rna.tf32.f32 %0, %1;" : "=r"(r) : "f"(x));
    return r;
}
__device__ __forceinline__ void mma_tf32(float* c,
                                         uint32_t a0, uint32_t a1, uint32_t a2, uint32_t a3,
                                         uint32_t b0, uint32_t b1) {
    asm volatile(
        "mma.sync.aligned.m16n8k8.row.col.f32.tf32.tf32.f32 "
        "{%0,%1,%2,%3}, {%4,%5,%6,%7}, {%8,%9}, {%0,%1,%2,%3};"
        : "+f"(c[0]), "+f"(c[1]), "+f"(c[2]), "+f"(c[3])
        : "r"(a0), "r"(a1), "r"(a2), "r"(a3), "r"(b0), "r"(b1));
}
__device__ __forceinline__ void cp16(uint32_t saddr, const void* g) {
    asm volatile("cp.async.cg.shared.global [%0], [%1], 16;" :: "r"(saddr), "l"(g));
}

// ---------------------------------------------------------------------------
// fp32 -> tf32 bit-pattern convert (vectorized)
// ---------------------------------------------------------------------------
__global__ void cvt_kernel(const float4* __restrict__ src,
                           float4* __restrict__ dst, int n4) {
    int i = blockIdx.x * blockDim.x + threadIdx.x;
    if (i >= n4) return;
    float4 v = src[i];
    v.x = __uint_as_float(f2tf(v.x));
    v.y = __uint_as_float(f2tf(v.y));
    v.z = __uint_as_float(f2tf(v.z));
    v.w = __uint_as_float(f2tf(v.w));
    dst[i] = v;
}

// ---------------------------------------------------------------------------
// RoPE table
// ---------------------------------------------------------------------------
__global__ void rope_table_kernel() {
    int i = blockIdx.x * blockDim.x + threadIdx.x;
    if (i >= T_SEQ * H_DIM) return;
    int t = i >> 6;
    int d = i & 63;
    double f = pow(10000.0, -(double)(d & 31) / 32.0);
    double ang = (double)t * f;
    g_cos[i] = (float)cos(ang);
    g_sin[i] = (float)sin(ang);
}

// ---------------------------------------------------------------------------
// Shared GEMM mainloop pieces (R10 config: 128x128 tile, BK=16, 256 threads,
// warp tile 32x64, 3-stage cp.async).
// ---------------------------------------------------------------------------
#define ALD 20
#define TILE_F (128 * ALD)          // 2560
#define STAGE_F (2 * TILE_F)        // 5120
#define GEMM_SMEM_BYTES (3 * STAGE_F * 4)  // 61440

__device__ __forceinline__ void gemm_load_stage(
    float* sm, int s, const float* A, const float* B,
    int K, int bm, int bn, int k0, int t) {
    float* base = sm + s * STAGE_F;
#pragma unroll
    for (int c = 0; c < 2; c++) {
        int cc = t * 2 + c;
        int row = cc >> 2;
        int k4 = (cc & 3) * 4;
        uint32_t so = (uint32_t)__cvta_generic_to_shared(base + row * ALD + k4);
        cp16(so,              A + (size_t)(bm + row) * K + k0 + k4);
        cp16(so + TILE_F * 4, B + (size_t)(bn + row) * K + k0 + k4);
    }
    asm volatile("cp.async.commit_group;");
}

// Mainloop macro body shared by both GEMM kernels (accumulates into c[2][8][4]).
#define GEMM_MAINLOOP(A, B, K, bm, bn)                                         \
    int nkt = (K) / 16;                                                        \
    gemm_load_stage(sm, 0, A, B, K, bm, bn, 0, t);                             \
    gemm_load_stage(sm, 1, A, B, K, bm, bn, 16, t);                            \
    for (int kt = 0; kt < nkt; kt++) {                                         \
        asm volatile("cp.async.wait_group 1;");                                \
        __syncthreads();                                                       \
        if (kt + 2 < nkt)                                                      \
            gemm_load_stage(sm, (kt + 2) % 3, A, B, K, bm, bn, (kt + 2) * 16, t); \
        else                                                                   \
            asm volatile("cp.async.commit_group;");                            \
        float* As = sm + (kt % 3) * STAGE_F;                                   \
        float* Bs = As + TILE_F;                                               \
        _Pragma("unroll")                                                      \
        for (int ks = 0; ks < 2; ks++) {                                       \
            int kb = ks * 8;                                                   \
            uint32_t ah[2][4];                                                 \
            _Pragma("unroll")                                                  \
            for (int mt = 0; mt < 2; mt++) {                                   \
                int row = mw + mt * 16 + gid;                                  \
                ah[mt][0] = __float_as_uint(As[row * ALD + kb + tig]);         \
                ah[mt][1] = __float_as_uint(As[(row + 8) * ALD + kb + tig]);   \
                ah[mt][2] = __float_as_uint(As[row * ALD + kb + tig + 4]);     \
                ah[mt][3] = __float_as_uint(As[(row + 8) * ALD + kb + tig + 4]); \
            }                                                                  \
            uint32_t bh[8][2];                                                 \
            _Pragma("unroll")                                                  \
            for (int nt = 0; nt < 8; nt++) {                                   \
                int n = nw + nt * 8 + gid;                                     \
                bh[nt][0] = __float_as_uint(Bs[n * ALD + kb + tig]);           \
                bh[nt][1] = __float_as_uint(Bs[n * ALD + kb + tig + 4]);       \
            }                                                                  \
            _Pragma("unroll")                                                  \
            for (int mt = 0; mt < 2; mt++)                                     \
                _Pragma("unroll")                                              \
                for (int nt = 0; nt < 8; nt++)                                 \
                    mma_tf32(c[mt][nt], ah[mt][0], ah[mt][1], ah[mt][2],       \
                             ah[mt][3], bh[nt][0], bh[nt][1]);                 \
        }                                                                      \
    }

// ---------------------------------------------------------------------------
// Proj GEMM: plain fp32 epilogue to Cm.
// ---------------------------------------------------------------------------
__global__ __launch_bounds__(256)
void sgemm_tf32(const float* __restrict__ A, const float* __restrict__ B,
                float* __restrict__ Cm, int M, int N, int K) {
    extern __shared__ __align__(16) float sm[];
    int t = threadIdx.x;
    int lane = t & 31, w = t >> 5;
    int gid = lane >> 2, tig = lane & 3;
    int mw = (w & 3) * 32;
    int nw = (w >> 2) * 64;
    int bm = blockIdx.y * 128, bn = blockIdx.x * 128;
    float c[2][8][4] = {};

    GEMM_MAINLOOP(A, B, K, bm, bn)

#pragma unroll
    for (int mt = 0; mt < 2; mt++) {
        int row = bm + mw + mt * 16 + gid;
#pragma unroll
        for (int nt = 0; nt < 8; nt++) {
            int col = bn + nw + nt * 8 + 2 * tig;
            *(float2*)&Cm[(size_t)row * N + col] =
                make_float2(c[mt][nt][0], c[mt][nt][1]);
            *(float2*)&Cm[(size_t)(row + 8) * N + col] =
                make_float2(c[mt][nt][2], c[mt][nt][3]);
        }
    }
}

// ---------------------------------------------------------------------------
// QKV GEMM with fused RoPE epilogue. N = 3072 (q|k|v sections).
// Warp's 64-col block lies entirely in one (section, head). Rotation partner
// of register c[mt][nt][j] (col d) is c[mt][nt^4][j] (col d^32) — in-thread.
// Writes tf32 patterns directly to g_q (pre-scaled 1/8), g_k, g_v in [B,H,T,D].
// ---------------------------------------------------------------------------
__global__ __launch_bounds__(256)
void sgemm_qkv_rope(const float* __restrict__ A, const float* __restrict__ B,
                    int M, int N, int K) {
    extern __shared__ __align__(16) float sm[];
    int t = threadIdx.x;
    int lane = t & 31, w = t >> 5;
    int gid = lane >> 2, tig = lane & 3;
    int mw = (w & 3) * 32;
    int nw = (w >> 2) * 64;
    int bm = blockIdx.y * 128, bn = blockIdx.x * 128;
    float c[2][8][4] = {};

    GEMM_MAINLOOP(A, B, K, bm, bn)

    int colbase = bn + nw;               // 64-aligned
    int sec = colbase >> 10;             // 0=q, 1=k, 2=v
    int h   = (colbase & 1023) >> 6;

#pragma unroll
    for (int mt = 0; mt < 2; mt++) {
        int row0 = bm + mw + mt * 16 + gid;
        int row1 = row0 + 8;
        int b0 = row0 >> 11, t0 = row0 & 2047;
        int b1 = row1 >> 11, t1 = row1 & 2047;
        size_t ob0 = ((size_t)(b0 * NHEAD + h) * T_SEQ + t0) * H_DIM;
        size_t ob1 = ((size_t)(b1 * NHEAD + h) * T_SEQ + t1) * H_DIM;

        if (sec == 2) {
#pragma unroll
            for (int nt = 0; nt < 8; nt++) {
                int d = nt * 8 + 2 * tig;
                *(float2*)&g_v[ob0 + d] =
                    make_float2(__uint_as_float(f2tf(c[mt][nt][0])),
                                __uint_as_float(f2tf(c[mt][nt][1])));
                *(float2*)&g_v[ob1 + d] =
                    make_float2(__uint_as_float(f2tf(c[mt][nt][2])),
                                __uint_as_float(f2tf(c[mt][nt][3])));
            }
        } else {
            float* dst = (sec == 0) ? g_q : g_k;
#pragma unroll
            for (int nt = 0; nt < 8; nt++) {
                int d = nt * 8 + 2 * tig;
                float sgn = (nt < 4) ? -1.f : 1.f;   // d<32 pairs with -x[d+32]
                int po = nt ^ 4;
                float cs00 = g_cos[t0 * 64 + d], cs01 = g_cos[t0 * 64 + d + 1];
                float sn00 = g_sin[t0 * 64 + d], sn01 = g_sin[t0 * 64 + d + 1];
                float cs10 = g_cos[t1 * 64 + d], cs11 = g_cos[t1 * 64 + d + 1];
                float sn10 = g_sin[t1 * 64 + d], sn11 = g_sin[t1 * 64 + d + 1];
                float v0 = c[mt][nt][0] * cs00 + sgn * c[mt][po][0] * sn00;
                float v1 = c[mt][nt][1] * cs01 + sgn * c[mt][po][1] * sn01;
                float v2 = c[mt][nt][2] * cs10 + sgn * c[mt][po][2] * sn10;
                float v3 = c[mt][nt][3] * cs11 + sgn * c[mt][po][3] * sn11;
                if (sec == 0) {
                    v0 *= 0.125f; v1 *= 0.125f; v2 *= 0.125f; v3 *= 0.125f;
                }
                *(float2*)&dst[ob0 + d] =
                    make_float2(__uint_as_float(f2tf(v0)),
                                __uint_as_float(f2tf(v1)));
                *(float2*)&dst[ob1 + d] =
                    make_float2(__uint_as_float(f2tf(v2)),
                                __uint_as_float(f2tf(v3)));
            }
        }
    }
}

// ---------------------------------------------------------------------------
// Flash attention (causal), tf32 mma, cp.async double-buffered K/V.
// Block 256 threads (8 warps), 128 Q rows (16/warp), 64-key tiles.
// P never touches smem (shfl permutation). UNCHANGED from R13.
// ---------------------------------------------------------------------------
#define KS_LD 68
#define VS_LD 72
#define KT_F (64 * KS_LD)                 // 4352
#define VT_F (64 * VS_LD)                 // 4608
#define SM_V_OFF (2 * KT_F)
#define ATTN_SMEM_FLOATS (SM_V_OFF + 2 * VT_F)   // 17920 floats = 71680 B

__device__ __forceinline__ void attn_load_tile(
    float* Ksm, float* Vsm, const float* Kb, const float* Vb, int kt, int t) {
    int row = t >> 2, dc = (t & 3) * 16;
    const float* kp = Kb + ((size_t)kt * 64 + row) * H_DIM + dc;
    const float* vp = Vb + ((size_t)kt * 64 + row) * H_DIM + dc;
    uint32_t ks = (uint32_t)__cvta_generic_to_shared(Ksm + row * KS_LD + dc);
    uint32_t vs = (uint32_t)__cvta_generic_to_shared(Vsm + row * VS_LD + dc);
#pragma unroll
    for (int j = 0; j < 4; j++) {
        cp16(ks + j * 16, kp + j * 4);
        cp16(vs + j * 16, vp + j * 4);
    }
    asm volatile("cp.async.commit_group;");
}

__global__ __launch_bounds__(256)
void attn_mma_kernel(const float* __restrict__ Q, const float* __restrict__ Kg,
                     const float* __restrict__ Vg, float* __restrict__ Yt) {
    extern __shared__ __align__(16) float sm[];

    int t = threadIdx.x;
    int lane = t & 31, w = t >> 5;
    int gid = lane >> 2, tig = lane & 3;
    int qt = gridDim.x - 1 - blockIdx.x;   // heavy-first
    int bh = blockIdx.y;
    int wrow = w * 16;

    const float* Qb = Q  + (size_t)bh * T_SEQ * H_DIM;
    const float* Kb = Kg + (size_t)bh * T_SEQ * H_DIM;
    const float* Vb = Vg + (size_t)bh * T_SEQ * H_DIM;

    int r0g = qt * 128 + wrow + gid;
    int r1g = r0g + 8;
    uint32_t qa[8][4];
    {
        const float* qp0 = Qb + (size_t)r0g * H_DIM;
        const float* qp1 = Qb + (size_t)r1g * H_DIM;
#pragma unroll
        for (int ks = 0; ks < 8; ks++) {
            int kk = ks * 8 + tig;
            qa[ks][0] = __float_as_uint(qp0[kk]);
            qa[ks][1] = __float_as_uint(qp1[kk]);
            qa[ks][2] = __float_as_uint(qp0[kk + 4]);
            qa[ks][3] = __float_as_uint(qp1[kk + 4]);
        }
    }

    float o[8][4] = {};
    float m0 = -INFINITY, m1 = -INFINITY;
    float l0 = 0.f, l1 = 0.f;

    int srcA = (lane & ~3) | (tig >> 1);   // cols tig
    int srcB = srcA + 2;                   // cols tig+4
    bool oddc = (tig & 1);

    int ktmax = 2 * qt + 1;
    attn_load_tile(sm, sm + SM_V_OFF, Kb, Vb, 0, t);

    for (int kt = 0; kt <= ktmax; kt++) {
        asm volatile("cp.async.wait_group 0;");
        __syncthreads();
        if (kt + 1 <= ktmax)
            attn_load_tile(sm + ((kt + 1) & 1) * KT_F,
                           sm + SM_V_OFF + ((kt + 1) & 1) * VT_F,
                           Kb, Vb, kt + 1, t);
        float* Ksm = sm + (kt & 1) * KT_F;
        float* Vsm = sm + SM_V_OFF + (kt & 1) * VT_F;

        // S = Q K^T (scale folded into Q)
        float s[8][4] = {};
#pragma unroll
        for (int ks = 0; ks < 8; ks++) {
            int kk = ks * 8 + tig;
#pragma unroll
            for (int nt = 0; nt < 8; nt++) {
                int n = nt * 8 + gid;
                uint32_t b0 = __float_as_uint(Ksm[n * KS_LD + kk]);
                uint32_t b1 = __float_as_uint(Ksm[n * KS_LD + kk + 4]);
                mma_tf32(s[nt], qa[ks][0], qa[ks][1], qa[ks][2], qa[ks][3], b0, b1);
            }
        }

        if (kt * 64 + 63 > qt * 128 + wrow) {
#pragma unroll
            for (int nt = 0; nt < 8; nt++) {
                int col = kt * 64 + nt * 8 + 2 * tig;
                if (col > r0g)     s[nt][0] = -INFINITY;
                if (col + 1 > r0g) s[nt][1] = -INFINITY;
                if (col > r1g)     s[nt][2] = -INFINITY;
                if (col + 1 > r1g) s[nt][3] = -INFINITY;
            }
        }

        float mt0 = -INFINITY, mt1 = -INFINITY;
#pragma unroll
        for (int nt = 0; nt < 8; nt++) {
            mt0 = fmaxf(mt0, fmaxf(s[nt][0], s[nt][1]));
            mt1 = fmaxf(mt1, fmaxf(s[nt][2], s[nt][3]));
        }
        mt0 = fmaxf(mt0, __shfl_xor_sync(0xffffffffu, mt0, 1));
        mt0 = fmaxf(mt0, __shfl_xor_sync(0xffffffffu, mt0, 2));
        mt1 = fmaxf(mt1, __shfl_xor_sync(0xffffffffu, mt1, 1));
        mt1 = fmaxf(mt1, __shfl_xor_sync(0xffffffffu, mt1, 2));

        float mn0 = fmaxf(m0, mt0), mn1 = fmaxf(m1, mt1);
        float al0 = __expf(m0 - mn0), al1 = __expf(m1 - mn1);
        m0 = mn0; m1 = mn1;

        float ls0 = 0.f, ls1 = 0.f;
#pragma unroll
        for (int nt = 0; nt < 8; nt++) {
            s[nt][0] = __expf(s[nt][0] - mn0);
            s[nt][1] = __expf(s[nt][1] - mn0);
            s[nt][2] = __expf(s[nt][2] - mn1);
            s[nt][3] = __expf(s[nt][3] - mn1);
            ls0 += s[nt][0] + s[nt][1];
            ls1 += s[nt][2] + s[nt][3];
        }
        ls0 += __shfl_xor_sync(0xffffffffu, ls0, 1);
        ls0 += __shfl_xor_sync(0xffffffffu, ls0, 2);
        ls1 += __shfl_xor_sync(0xffffffffu, ls1, 1);
        ls1 += __shfl_xor_sync(0xffffffffu, ls1, 2);
        l0 = l0 * al0 + ls0;
        l1 = l1 * al1 + ls1;

#pragma unroll
        for (int nt = 0; nt < 8; nt++) {
            o[nt][0] *= al0; o[nt][1] *= al0;
            o[nt][2] *= al1; o[nt][3] *= al1;
        }

        // O += P * V ; P fragments built by intra-quad shfl permutation.
#pragma unroll
        for (int ks = 0; ks < 8; ks++) {
            float c0 = __uint_as_float(f2tf(s[ks][0]));
            float c1 = __uint_as_float(f2tf(s[ks][1]));
            float c2 = __uint_as_float(f2tf(s[ks][2]));
            float c3 = __uint_as_float(f2tf(s[ks][3]));
            float a00 = __shfl_sync(0xffffffffu, c0, srcA);
            float a01 = __shfl_sync(0xffffffffu, c1, srcA);
            float a10 = __shfl_sync(0xffffffffu, c2, srcA);
            float a11 = __shfl_sync(0xffffffffu, c3, srcA);
            float b00 = __shfl_sync(0xffffffffu, c0, srcB);
            float b01 = __shfl_sync(0xffffffffu, c1, srcB);
            float b10 = __shfl_sync(0xffffffffu, c2, srcB);
            float b11 = __shfl_sync(0xffffffffu, c3, srcB);
            uint32_t pa0 = __float_as_uint(oddc ? a01 : a00);
            uint32_t pa1 = __float_as_uint(oddc ? a11 : a10);
            uint32_t pa2 = __float_as_uint(oddc ? b01 : b00);
            uint32_t pa3 = __float_as_uint(oddc ? b11 : b10);
            int kk = ks * 8;
#pragma unroll
            for (int nt = 0; nt < 8; nt++) {
                int d = nt * 8 + gid;
                uint32_t b0 = __float_as_uint(Vsm[(kk + tig) * VS_LD + d]);
                uint32_t b1 = __float_as_uint(Vsm[(kk + tig + 4) * VS_LD + d]);
                mma_tf32(o[nt], pa0, pa1, pa2, pa3, b0, b1);
            }
        }
    }

    // finalize: divide by l, write tf32 pattern into Yt [B,T,C]
    float inv0 = 1.f / l0, inv1 = 1.f / l1;
    int b = bh >> 4, h = bh & 15;
    size_t off0 = ((size_t)b * T_SEQ + r0g) * C_EMB + h * 64;
    size_t off1 = ((size_t)b * T_SEQ + r1g) * C_EMB + h * 64;
#pragma unroll
    for (int nt = 0; nt < 8; nt++) {
        int col = nt * 8 + 2 * tig;
        *(float2*)&Yt[off0 + col] =
            make_float2(__uint_as_float(f2tf(o[nt][0] * inv0)),
                        __uint_as_float(f2tf(o[nt][1] * inv0)));
        *(float2*)&Yt[off1 + col] =
            make_float2(__uint_as_float(f2tf(o[nt][2] * inv1)),
                        __uint_as_float(f2tf(o[nt][3] * inv1)));
    }
}

// ---------------------------------------------------------------------------
extern "C" void kernel_launch(void* const* d_in, const int* in_sizes, int n_in,
                              void* d_out, int out_size) {
    const float* x      = (const float*)d_in[0];
    const float* w_qkv  = (const float*)d_in[1];
    const float* w_proj = (const float*)d_in[2];
    float* out = (float*)d_out;

    float *p_xt, *p_wqt, *p_wpt, *p_q, *p_k, *p_v, *p_yt;
    cudaGetSymbolAddress((void**)&p_xt, g_xt);
    cudaGetSymbolAddress((void**)&p_wqt, g_wqt);
    cudaGetSymbolAddress((void**)&p_wpt, g_wpt);
    cudaGetSymbolAddress((void**)&p_q, g_q);
    cudaGetSymbolAddress((void**)&p_k, g_k);
    cudaGetSymbolAddress((void**)&p_v, g_v);
    cudaGetSymbolAddress((void**)&p_yt, g_yt);

    // RoPE tables + tf32 pre-conversion
    rope_table_kernel<<<(T_SEQ * H_DIM + 255) / 256, 256>>>();
    cvt_kernel<<<(M_TOT * C_EMB / 4 + 255) / 256, 256>>>(
        (const float4*)x, (float4*)p_xt, M_TOT * C_EMB / 4);
    cvt_kernel<<<(3 * C_EMB * C_EMB / 4 + 255) / 256, 256>>>(
        (const float4*)w_qkv, (float4*)p_wqt, 3 * C_EMB * C_EMB / 4);
    cvt_kernel<<<(C_EMB * C_EMB / 4 + 255) / 256, 256>>>(
        (const float4*)w_proj, (float4*)p_wpt, C_EMB * C_EMB / 4);

    cudaFuncSetAttribute(sgemm_qkv_rope,
                         cudaFuncAttributeMaxDynamicSharedMemorySize, GEMM_SMEM_BYTES);
    cudaFuncSetAttribute(sgemm_tf32,
                         cudaFuncAttributeMaxDynamicSharedMemorySize, GEMM_SMEM_BYTES);

    // QKV GEMM with fused RoPE epilogue -> g_q/g_k/g_v directly
    sgemm_qkv_rope<<<dim3((3 * C_EMB) / 128, M_TOT / 128), 256, GEMM_SMEM_BYTES>>>(
        p_xt, p_wqt, M_TOT, 3 * C_EMB, C_EMB);

    // Flash attention
    int smem_bytes = ATTN_SMEM_FLOATS * 4;   // 71680
    cudaFuncSetAttribute(attn_mma_kernel,
                         cudaFuncAttributeMaxDynamicSharedMemorySize, smem_bytes);
    attn_mma_kernel<<<dim3(T_SEQ / 128, B_SZ * NHEAD), 256, smem_bytes>>>(
        p_q, p_k, p_v, p_yt);

    // Proj GEMM: [4096,1024] x [1024,1024]^T -> out
    sgemm_tf32<<<dim3(C_EMB / 128, M_TOT / 128), 256, GEMM_SMEM_BYTES>>>(
        p_yt, p_wpt, out, M_TOT, C_EMB, C_EMB);
}

// round 15
// speedup vs baseline: 2.0887x; 1.8599x over previous
#include <cuda_runtime.h>
#include <cuda_fp16.h>
#include <math.h>
#include <stdint.h>

#define B_SZ   2
#define T_SEQ  2048
#define C_EMB  1024
#define NHEAD  16
#define H_DIM  64
#define M_TOT  (B_SZ * T_SEQ)   // 4096

// Scratch (static device arrays) — fp16 storage everywhere
__device__ __half g_xt[(size_t)M_TOT * C_EMB];
__device__ __half g_wqt[(size_t)3 * C_EMB * C_EMB];
__device__ __half g_wpt[(size_t)C_EMB * C_EMB];
__device__ __half g_q[(size_t)B_SZ * NHEAD * T_SEQ * H_DIM];  // [B,H,T,D], pre-scaled 1/8
__device__ __half g_k[(size_t)B_SZ * NHEAD * T_SEQ * H_DIM];  // [B,H,T,D]
__device__ __half g_v[(size_t)B_SZ * NHEAD * H_DIM * T_SEQ];  // [B,H,D,T]  (transposed!)
__device__ __half g_yt[(size_t)M_TOT * C_EMB];                // [B,T,C]
__device__ float  g_cos[T_SEQ * H_DIM];
__device__ float  g_sin[T_SEQ * H_DIM];

// ---------------------------------------------------------------------------
__device__ __forceinline__ uint32_t f2h2(float lo, float hi) {
    __half2 h = __floats2half2_rn(lo, hi);
    return *(uint32_t*)&h;
}
__device__ __forceinline__ void mma_f16(float* c,
                                        uint32_t a0, uint32_t a1, uint32_t a2, uint32_t a3,
                                        uint32_t b0, uint32_t b1) {
    asm volatile(
        "mma.sync.aligned.m16n8k16.row.col.f32.f16.f16.f32 "
        "{%0,%1,%2,%3}, {%4,%5,%6,%7}, {%8,%9}, {%0,%1,%2,%3};"
        : "+f"(c[0]), "+f"(c[1]), "+f"(c[2]), "+f"(c[3])
        : "r"(a0), "r"(a1), "r"(a2), "r"(a3), "r"(b0), "r"(b1));
}
__device__ __forceinline__ void cp16(uint32_t saddr, const void* g) {
    asm volatile("cp.async.cg.shared.global [%0], [%1], 16;" :: "r"(saddr), "l"(g));
}
__device__ __forceinline__ uint32_t ld32h(const __half* p) {
    return *(const uint32_t*)p;
}

// ---------------------------------------------------------------------------
// fp32 -> fp16 convert (vectorized: 4 floats -> 4 halves per thread)
// ---------------------------------------------------------------------------
__global__ void cvt_h_kernel(const float4* __restrict__ src,
                             uint2* __restrict__ dst, int n4) {
    int i = blockIdx.x * blockDim.x + threadIdx.x;
    if (i >= n4) return;
    float4 v = src[i];
    uint2 o;
    o.x = f2h2(v.x, v.y);
    o.y = f2h2(v.z, v.w);
    dst[i] = o;
}

// ---------------------------------------------------------------------------
// RoPE table
// ---------------------------------------------------------------------------
__global__ void rope_table_kernel() {
    int i = blockIdx.x * blockDim.x + threadIdx.x;
    if (i >= T_SEQ * H_DIM) return;
    int t = i >> 6;
    int d = i & 63;
    double f = pow(10000.0, -(double)(d & 31) / 32.0);
    double ang = (double)t * f;
    g_cos[i] = (float)cos(ang);
    g_sin[i] = (float)sin(ang);
}

// ---------------------------------------------------------------------------
// fp16 GEMM mainloop: C[M,N] = A[M,K] * B[N,K]^T, K in halves.
// 128x128 tile, BK=32 halves, 256 threads, warp tile 32x64, 3-stage cp.async.
// ---------------------------------------------------------------------------
#define ALDH 40
#define TILE_H (128 * ALDH)         // 5120 halves
#define STAGE_H (2 * TILE_H)        // 10240 halves
#define GEMM_SMEM_BYTES (3 * STAGE_H * 2)   // 61440 B

__device__ __forceinline__ void gemm_load_stage_h(
    __half* smh, int s, const __half* A, const __half* B,
    int K, int bm, int bn, int k0, int t) {
    __half* base = smh + s * STAGE_H;
#pragma unroll
    for (int c = 0; c < 2; c++) {
        int id = t * 2 + c;            // 0..511
        int row = id >> 2;             // 0..127
        int ko = (id & 3) * 8;         // 0,8,16,24 halves
        uint32_t so = (uint32_t)__cvta_generic_to_shared(base + row * ALDH + ko);
        cp16(so,              A + (size_t)(bm + row) * K + k0 + ko);
        cp16(so + TILE_H * 2, B + (size_t)(bn + row) * K + k0 + ko);
    }
    asm volatile("cp.async.commit_group;");
}

#define GEMM_MAINLOOP_H(A, B, K, bm, bn)                                       \
    int nkt = (K) / 32;                                                        \
    gemm_load_stage_h(smh, 0, A, B, K, bm, bn, 0, t);                          \
    gemm_load_stage_h(smh, 1, A, B, K, bm, bn, 32, t);                         \
    for (int kt = 0; kt < nkt; kt++) {                                         \
        asm volatile("cp.async.wait_group 1;");                                \
        __syncthreads();                                                       \
        if (kt + 2 < nkt)                                                      \
            gemm_load_stage_h(smh, (kt + 2) % 3, A, B, K, bm, bn,              \
                              (kt + 2) * 32, t);                               \
        else                                                                   \
            asm volatile("cp.async.commit_group;");                            \
        __half* As = smh + (kt % 3) * STAGE_H;                                 \
        __half* Bs = As + TILE_H;                                              \
        _Pragma("unroll")                                                      \
        for (int ks = 0; ks < 2; ks++) {                                       \
            int kb = ks * 16;                                                  \
            uint32_t ah[2][4];                                                 \
            _Pragma("unroll")                                                  \
            for (int mt = 0; mt < 2; mt++) {                                   \
                int row = mw + mt * 16 + gid;                                  \
                ah[mt][0] = ld32h(As + row * ALDH + kb + 2 * tig);             \
                ah[mt][1] = ld32h(As + (row + 8) * ALDH + kb + 2 * tig);       \
                ah[mt][2] = ld32h(As + row * ALDH + kb + 2 * tig + 8);         \
                ah[mt][3] = ld32h(As + (row + 8) * ALDH + kb + 2 * tig + 8);   \
            }                                                                  \
            uint32_t bh[8][2];                                                 \
            _Pragma("unroll")                                                  \
            for (int nt = 0; nt < 8; nt++) {                                   \
                int n = nw + nt * 8 + gid;                                     \
                bh[nt][0] = ld32h(Bs + n * ALDH + kb + 2 * tig);               \
                bh[nt][1] = ld32h(Bs + n * ALDH + kb + 2 * tig + 8);           \
            }                                                                  \
            _Pragma("unroll")                                                  \
            for (int mt = 0; mt < 2; mt++)                                     \
                _Pragma("unroll")                                              \
                for (int nt = 0; nt < 8; nt++)                                 \
                    mma_f16(c[mt][nt], ah[mt][0], ah[mt][1], ah[mt][2],        \
                            ah[mt][3], bh[nt][0], bh[nt][1]);                  \
        }                                                                      \
    }

// ---------------------------------------------------------------------------
// Proj GEMM: fp16 inputs, fp32 output.
// ---------------------------------------------------------------------------
__global__ __launch_bounds__(256)
void sgemm_f16(const __half* __restrict__ A, const __half* __restrict__ B,
               float* __restrict__ Cm, int M, int N, int K) {
    extern __shared__ __align__(16) __half smh[];
    int t = threadIdx.x;
    int lane = t & 31, w = t >> 5;
    int gid = lane >> 2, tig = lane & 3;
    int mw = (w & 3) * 32;
    int nw = (w >> 2) * 64;
    int bm = blockIdx.y * 128, bn = blockIdx.x * 128;
    float c[2][8][4] = {};

    GEMM_MAINLOOP_H(A, B, K, bm, bn)

#pragma unroll
    for (int mt = 0; mt < 2; mt++) {
        int row = bm + mw + mt * 16 + gid;
#pragma unroll
        for (int nt = 0; nt < 8; nt++) {
            int col = bn + nw + nt * 8 + 2 * tig;
            *(float2*)&Cm[(size_t)row * N + col] =
                make_float2(c[mt][nt][0], c[mt][nt][1]);
            *(float2*)&Cm[(size_t)(row + 8) * N + col] =
                make_float2(c[mt][nt][2], c[mt][nt][3]);
        }
    }
}

// ---------------------------------------------------------------------------
// QKV GEMM with fused RoPE epilogue -> g_q (scaled 1/8), g_k [B,H,T,D] and
// g_v TRANSPOSED [B,H,D,T], all fp16. Rotation partner c[mt][nt^4][j] in-thread.
// ---------------------------------------------------------------------------
__global__ __launch_bounds__(256)
void sgemm_qkv_rope(const __half* __restrict__ A, const __half* __restrict__ B,
                    int M, int N, int K) {
    extern __shared__ __align__(16) __half smh[];
    int t = threadIdx.x;
    int lane = t & 31, w = t >> 5;
    int gid = lane >> 2, tig = lane & 3;
    int mw = (w & 3) * 32;
    int nw = (w >> 2) * 64;
    int bm = blockIdx.y * 128, bn = blockIdx.x * 128;
    float c[2][8][4] = {};

    GEMM_MAINLOOP_H(A, B, K, bm, bn)

    int colbase = bn + nw;               // 64-aligned
    int sec = colbase >> 10;             // 0=q, 1=k, 2=v
    int h   = (colbase & 1023) >> 6;

#pragma unroll
    for (int mt = 0; mt < 2; mt++) {
        int row0 = bm + mw + mt * 16 + gid;
        int row1 = row0 + 8;
        int b0 = row0 >> 11, t0 = row0 & 2047;
        int t1 = row1 & 2047;            // same batch as row0 (128 | 2048)

        if (sec == 2) {
            size_t vb = (size_t)(b0 * NHEAD + h) * H_DIM * T_SEQ;
#pragma unroll
            for (int nt = 0; nt < 8; nt++) {
                int d = nt * 8 + 2 * tig;
                g_v[vb + (size_t)d * T_SEQ + t0]       = __float2half_rn(c[mt][nt][0]);
                g_v[vb + (size_t)(d + 1) * T_SEQ + t0] = __float2half_rn(c[mt][nt][1]);
                g_v[vb + (size_t)d * T_SEQ + t1]       = __float2half_rn(c[mt][nt][2]);
                g_v[vb + (size_t)(d + 1) * T_SEQ + t1] = __float2half_rn(c[mt][nt][3]);
            }
        } else {
            __half* dst = (sec == 0) ? g_q : g_k;
            size_t ob0 = ((size_t)(b0 * NHEAD + h) * T_SEQ + t0) * H_DIM;
            size_t ob1 = ((size_t)(b0 * NHEAD + h) * T_SEQ + t1) * H_DIM;
#pragma unroll
            for (int nt = 0; nt < 8; nt++) {
                int d = nt * 8 + 2 * tig;
                float sgn = (nt < 4) ? -1.f : 1.f;
                int po = nt ^ 4;
                float cs00 = g_cos[t0 * 64 + d], cs01 = g_cos[t0 * 64 + d + 1];
                float sn00 = g_sin[t0 * 64 + d], sn01 = g_sin[t0 * 64 + d + 1];
                float cs10 = g_cos[t1 * 64 + d], cs11 = g_cos[t1 * 64 + d + 1];
                float sn10 = g_sin[t1 * 64 + d], sn11 = g_sin[t1 * 64 + d + 1];
                float v0 = c[mt][nt][0] * cs00 + sgn * c[mt][po][0] * sn00;
                float v1 = c[mt][nt][1] * cs01 + sgn * c[mt][po][1] * sn01;
                float v2 = c[mt][nt][2] * cs10 + sgn * c[mt][po][2] * sn10;
                float v3 = c[mt][nt][3] * cs11 + sgn * c[mt][po][3] * sn11;
                if (sec == 0) {
                    v0 *= 0.125f; v1 *= 0.125f; v2 *= 0.125f; v3 *= 0.125f;
                }
                *(uint32_t*)&dst[ob0 + d] = f2h2(v0, v1);
                *(uint32_t*)&dst[ob1 + d] = f2h2(v2, v3);
            }
        }
    }
}

// ---------------------------------------------------------------------------
// Flash attention (causal), fp16 m16n8k16 mma, cp.async double-buffered K/V.
// Block 256 threads (8 warps), 128 Q rows (16/warp), 64-key tiles.
// P C-fragments map DIRECTLY onto fp16 A-fragments (no shfl, no smem).
// K smem [n][k]; V smem [d][t] (gmem pre-transposed).
// ---------------------------------------------------------------------------
#define KLDH 72
#define KT_H (64 * KLDH)                  // 4608 halves (9216 B)
#define SM_V_OFFH (2 * KT_H)
#define ATTN_SMEM_BYTES ((SM_V_OFFH + 2 * KT_H) * 2)   // 36864 B

__device__ __forceinline__ void attn_load_tile(
    __half* Ksm, __half* Vsm, const __half* Kb, const __half* Vt, int kt, int t) {
#pragma unroll
    for (int c = 0; c < 2; c++) {
        int id = t * 2 + c;            // 0..511
        int row = id >> 3;             // 0..63
        int ko = (id & 7) * 8;         // 0..56 halves
        uint32_t ks = (uint32_t)__cvta_generic_to_shared(Ksm + row * KLDH + ko);
        uint32_t vs = (uint32_t)__cvta_generic_to_shared(Vsm + row * KLDH + ko);
        cp16(ks, Kb + ((size_t)kt * 64 + row) * H_DIM + ko);
        cp16(vs, Vt + (size_t)row * T_SEQ + kt * 64 + ko);
    }
    asm volatile("cp.async.commit_group;");
}

__global__ __launch_bounds__(256)
void attn_mma_kernel(const __half* __restrict__ Q, const __half* __restrict__ Kg,
                     const __half* __restrict__ Vg, __half* __restrict__ Yt) {
    extern __shared__ __align__(16) __half smh[];

    int t = threadIdx.x;
    int lane = t & 31, w = t >> 5;
    int gid = lane >> 2, tig = lane & 3;
    int qt = gridDim.x - 1 - blockIdx.x;   // heavy-first
    int bh = blockIdx.y;
    int wrow = w * 16;

    const __half* Qb = Q  + (size_t)bh * T_SEQ * H_DIM;
    const __half* Kb = Kg + (size_t)bh * T_SEQ * H_DIM;
    const __half* Vt = Vg + (size_t)bh * H_DIM * T_SEQ;

    int r0g = qt * 128 + wrow + gid;
    int r1g = r0g + 8;

    // Q fragments: 4 k16-chunks x 4 regs (half2), direct from gmem
    uint32_t qa[4][4];
#pragma unroll
    for (int kc = 0; kc < 4; kc++) {
        const __half* q0 = Qb + (size_t)r0g * H_DIM + kc * 16 + 2 * tig;
        const __half* q1 = Qb + (size_t)r1g * H_DIM + kc * 16 + 2 * tig;
        qa[kc][0] = ld32h(q0);
        qa[kc][1] = ld32h(q1);
        qa[kc][2] = ld32h(q0 + 8);
        qa[kc][3] = ld32h(q1 + 8);
    }

    float o[8][4] = {};
    float m0 = -INFINITY, m1 = -INFINITY;
    float l0 = 0.f, l1 = 0.f;

    int ktmax = 2 * qt + 1;
    attn_load_tile(smh, smh + SM_V_OFFH, Kb, Vt, 0, t);

    for (int kt = 0; kt <= ktmax; kt++) {
        asm volatile("cp.async.wait_group 0;");
        __syncthreads();
        if (kt + 1 <= ktmax)
            attn_load_tile(smh + ((kt + 1) & 1) * KT_H,
                           smh + SM_V_OFFH + ((kt + 1) & 1) * KT_H,
                           Kb, Vt, kt + 1, t);
        __half* Ksm = smh + (kt & 1) * KT_H;
        __half* Vsm = smh + SM_V_OFFH + (kt & 1) * KT_H;

        // S = Q K^T (scale folded into Q)
        float s[8][4] = {};
#pragma unroll
        for (int kc = 0; kc < 4; kc++) {
            int kb = kc * 16;
#pragma unroll
            for (int nt = 0; nt < 8; nt++) {
                int n = nt * 8 + gid;
                uint32_t b0 = ld32h(Ksm + n * KLDH + kb + 2 * tig);
                uint32_t b1 = ld32h(Ksm + n * KLDH + kb + 2 * tig + 8);
                mma_f16(s[nt], qa[kc][0], qa[kc][1], qa[kc][2], qa[kc][3], b0, b1);
            }
        }

        if (kt * 64 + 63 > qt * 128 + wrow) {
#pragma unroll
            for (int nt = 0; nt < 8; nt++) {
                int col = kt * 64 + nt * 8 + 2 * tig;
                if (col > r0g)     s[nt][0] = -INFINITY;
                if (col + 1 > r0g) s[nt][1] = -INFINITY;
                if (col > r1g)     s[nt][2] = -INFINITY;
                if (col + 1 > r1g) s[nt][3] = -INFINITY;
            }
        }

        float mt0 = -INFINITY, mt1 = -INFINITY;
#pragma unroll
        for (int nt = 0; nt < 8; nt++) {
            mt0 = fmaxf(mt0, fmaxf(s[nt][0], s[nt][1]));
            mt1 = fmaxf(mt1, fmaxf(s[nt][2], s[nt][3]));
        }
        mt0 = fmaxf(mt0, __shfl_xor_sync(0xffffffffu, mt0, 1));
        mt0 = fmaxf(mt0, __shfl_xor_sync(0xffffffffu, mt0, 2));
        mt1 = fmaxf(mt1, __shfl_xor_sync(0xffffffffu, mt1, 1));
        mt1 = fmaxf(mt1, __shfl_xor_sync(0xffffffffu, mt1, 2));

        float mn0 = fmaxf(m0, mt0), mn1 = fmaxf(m1, mt1);
        float al0 = __expf(m0 - mn0), al1 = __expf(m1 - mn1);
        m0 = mn0; m1 = mn1;

        float ls0 = 0.f, ls1 = 0.f;
#pragma unroll
        for (int nt = 0; nt < 8; nt++) {
            s[nt][0] = __expf(s[nt][0] - mn0);
            s[nt][1] = __expf(s[nt][1] - mn0);
            s[nt][2] = __expf(s[nt][2] - mn1);
            s[nt][3] = __expf(s[nt][3] - mn1);
            ls0 += s[nt][0] + s[nt][1];
            ls1 += s[nt][2] + s[nt][3];
        }
        ls0 += __shfl_xor_sync(0xffffffffu, ls0, 1);
        ls0 += __shfl_xor_sync(0xffffffffu, ls0, 2);
        ls1 += __shfl_xor_sync(0xffffffffu, ls1, 1);
        ls1 += __shfl_xor_sync(0xffffffffu, ls1, 2);
        l0 = l0 * al0 + ls0;
        l1 = l1 * al1 + ls1;

#pragma unroll
        for (int nt = 0; nt < 8; nt++) {
            o[nt][0] *= al0; o[nt][1] *= al0;
            o[nt][2] *= al1; o[nt][3] *= al1;
        }

        // O += P * V ; P C-frag == fp16 A-frag layout (direct pack, no shfl)
#pragma unroll
        for (int kc = 0; kc < 4; kc++) {
            uint32_t pa0 = f2h2(s[2 * kc][0],     s[2 * kc][1]);
            uint32_t pa1 = f2h2(s[2 * kc][2],     s[2 * kc][3]);
            uint32_t pa2 = f2h2(s[2 * kc + 1][0], s[2 * kc + 1][1]);
            uint32_t pa3 = f2h2(s[2 * kc + 1][2], s[2 * kc + 1][3]);
            int kb = kc * 16;
#pragma unroll
            for (int nt = 0; nt < 8; nt++) {
                int d = nt * 8 + gid;
                uint32_t b0 = ld32h(Vsm + d * KLDH + kb + 2 * tig);
                uint32_t b1 = ld32h(Vsm + d * KLDH + kb + 2 * tig + 8);
                mma_f16(o[nt], pa0, pa1, pa2, pa3, b0, b1);
            }
        }
    }

    // finalize: divide by l, write fp16 into Yt [B,T,C]
    float inv0 = 1.f / l0, inv1 = 1.f / l1;
    int b = bh >> 4, h = bh & 15;
    size_t off0 = ((size_t)b * T_SEQ + r0g) * C_EMB + h * 64;
    size_t off1 = ((size_t)b * T_SEQ + r1g) * C_EMB + h * 64;
#pragma unroll
    for (int nt = 0; nt < 8; nt++) {
        int col = nt * 8 + 2 * tig;
        *(uint32_t*)&Yt[off0 + col] = f2h2(o[nt][0] * inv0, o[nt][1] * inv0);
        *(uint32_t*)&Yt[off1 + col] = f2h2(o[nt][2] * inv1, o[nt][3] * inv1);
    }
}

// ---------------------------------------------------------------------------
extern "C" void kernel_launch(void* const* d_in, const int* in_sizes, int n_in,
                              void* d_out, int out_size) {
    const float* x      = (const float*)d_in[0];
    const float* w_qkv  = (const float*)d_in[1];
    const float* w_proj = (const float*)d_in[2];
    float* out = (float*)d_out;

    __half *p_xt, *p_wqt, *p_wpt, *p_q, *p_k, *p_v, *p_yt;
    cudaGetSymbolAddress((void**)&p_xt, g_xt);
    cudaGetSymbolAddress((void**)&p_wqt, g_wqt);
    cudaGetSymbolAddress((void**)&p_wpt, g_wpt);
    cudaGetSymbolAddress((void**)&p_q, g_q);
    cudaGetSymbolAddress((void**)&p_k, g_k);
    cudaGetSymbolAddress((void**)&p_v, g_v);
    cudaGetSymbolAddress((void**)&p_yt, g_yt);

    // RoPE tables + fp16 pre-conversion
    rope_table_kernel<<<(T_SEQ * H_DIM + 255) / 256, 256>>>();
    cvt_h_kernel<<<(M_TOT * C_EMB / 4 + 255) / 256, 256>>>(
        (const float4*)x, (uint2*)p_xt, M_TOT * C_EMB / 4);
    cvt_h_kernel<<<(3 * C_EMB * C_EMB / 4 + 255) / 256, 256>>>(
        (const float4*)w_qkv, (uint2*)p_wqt, 3 * C_EMB * C_EMB / 4);
    cvt_h_kernel<<<(C_EMB * C_EMB / 4 + 255) / 256, 256>>>(
        (const float4*)w_proj, (uint2*)p_wpt, C_EMB * C_EMB / 4);

    cudaFuncSetAttribute(sgemm_qkv_rope,
                         cudaFuncAttributeMaxDynamicSharedMemorySize, GEMM_SMEM_BYTES);
    cudaFuncSetAttribute(sgemm_f16,
                         cudaFuncAttributeMaxDynamicSharedMemorySize, GEMM_SMEM_BYTES);

    // QKV GEMM with fused RoPE epilogue -> g_q/g_k/g_v
    sgemm_qkv_rope<<<dim3((3 * C_EMB) / 128, M_TOT / 128), 256, GEMM_SMEM_BYTES>>>(
        p_xt, p_wqt, M_TOT, 3 * C_EMB, C_EMB);

    // Flash attention (fp16)
    cudaFuncSetAttribute(attn_mma_kernel,
                         cudaFuncAttributeMaxDynamicSharedMemorySize, ATTN_SMEM_BYTES);
    attn_mma_kernel<<<dim3(T_SEQ / 128, B_SZ * NHEAD), 256, ATTN_SMEM_BYTES>>>(
        p_q, p_k, p_v, p_yt);

    // Proj GEMM: fp16 in, fp32 out
    sgemm_f16<<<dim3(C_EMB / 128, M_TOT / 128), 256, GEMM_SMEM_BYTES>>>(
        p_yt, p_wpt, out, M_TOT, C_EMB, C_EMB);
}